// round 13
// baseline (speedup 1.0000x reference)
#include <cuda_runtime.h>
#include <cuda_bf16.h>
#include <cstdint>
#include <math.h>

// Problem constants
#define B_   2
#define L_   2048
#define T_   4096        // B_*L_
#define DM_  1024
#define DI_  2048
#define DS_  16
#define DC_  4
#define DTR_ 64
#define V_   32000
#define DBC_ 96          // DTR + 2*DS

// ---------------- fp32 scratch ----------------
__device__ float g_xz [T_ * 2 * DI_];    // x | z
__device__ float g_x  [T_ * DI_];
__device__ float g_dbc[T_ * DBC_];
__device__ float g_dt [T_ * DI_];
__device__ float g_y  [T_ * DI_];

// ---------------- bf16 split scratch (hi/lo) ----------------
__device__ __nv_bfloat16 g_aemb_h[T_ * DM_],  g_aemb_l[T_ * DM_];
__device__ __nv_bfloat16 g_ax_h  [T_ * DI_],  g_ax_l  [T_ * DI_];
__device__ __nv_bfloat16 g_adt_h [T_ * DTR_], g_adt_l [T_ * DTR_];
__device__ __nv_bfloat16 g_ay_h  [T_ * DI_],  g_ay_l  [T_ * DI_];
__device__ __nv_bfloat16 g_ay2_h [T_ * DM_],  g_ay2_l [T_ * DM_];
__device__ __nv_bfloat16 g_win_h [2*DI_*DM_], g_win_l [2*DI_*DM_];
__device__ __nv_bfloat16 g_wxp_h [DBC_*DI_],  g_wxp_l [DBC_*DI_];
__device__ __nv_bfloat16 g_wdt_h [DI_*DTR_],  g_wdt_l [DI_*DTR_];
__device__ __nv_bfloat16 g_wout_h[DM_*DI_],   g_wout_l[DM_*DI_];
__device__ __nv_bfloat16 g_whead_h[(size_t)V_*DM_], g_whead_l[(size_t)V_*DM_];

// ---------------- selectors ----------------
enum Buf   { BUF_XZ = 0, BUF_X, BUF_DBC, BUF_DT, BUF_Y, BUF_EXT };
enum BPair { P_AEMB = 0, P_AX, P_ADT, P_AY, P_AY2,
             P_WIN, P_WXP, P_WDT, P_WOUT, P_WHEAD, P_NONE };

__device__ __forceinline__ float* buf_ptr_mut(int sel, float* ext) {
    switch (sel) {
        case BUF_XZ: return g_xz;   case BUF_X:  return g_x;
        case BUF_DBC: return g_dbc; case BUF_DT: return g_dt;
        case BUF_Y:  return g_y;    default:     return ext;
    }
}
__device__ __forceinline__ void bpair(int sel, __nv_bfloat16*& h, __nv_bfloat16*& l) {
    switch (sel) {
        case P_AEMB: h = g_aemb_h;  l = g_aemb_l;  break;
        case P_AX:   h = g_ax_h;    l = g_ax_l;    break;
        case P_ADT:  h = g_adt_h;   l = g_adt_l;   break;
        case P_AY:   h = g_ay_h;    l = g_ay_l;    break;
        case P_AY2:  h = g_ay2_h;   l = g_ay2_l;   break;
        case P_WIN:  h = g_win_h;   l = g_win_l;   break;
        case P_WXP:  h = g_wxp_h;   l = g_wxp_l;   break;
        case P_WDT:  h = g_wdt_h;   l = g_wdt_l;   break;
        case P_WOUT: h = g_wout_h;  l = g_wout_l;  break;
        case P_WHEAD: h = g_whead_h; l = g_whead_l; break;
        default:     h = nullptr;   l = nullptr;   break;
    }
}

// ---------------- math helpers ----------------
__device__ __forceinline__ float softplusf(float x) {
    return fmaxf(x, 0.f) + log1pf(__expf(-fabsf(x)));
}
__device__ __forceinline__ float siluf(float x) {
    return x / (1.f + __expf(-x));
}
__device__ __forceinline__ void split1(float x, __nv_bfloat16& h, __nv_bfloat16& l) {
    h = __float2bfloat16(x);
    l = __float2bfloat16(x - __bfloat162float(h));
}
__device__ __forceinline__ uint32_t smem_u32(const void* p) {
    uint32_t a;
    asm("{ .reg .u64 t; cvta.to.shared.u64 t, %1; cvt.u32.u64 %0, t; }" : "=r"(a) : "l"(p));
    return a;
}
__device__ __forceinline__ void cp16(uint32_t saddr, const void* g) {
    asm volatile("cp.async.cg.shared.global [%0], [%1], 16;" :: "r"(saddr), "l"(g));
}
__device__ __forceinline__ void cp16z(uint32_t saddr, const void* g, uint32_t srcsz) {
    asm volatile("cp.async.cg.shared.global [%0], [%1], 16, %2;"
                 :: "r"(saddr), "l"(g), "r"(srcsz));
}
__device__ __forceinline__ void ldsm4(uint32_t* r, uint32_t addr) {
    asm volatile("ldmatrix.sync.aligned.m8n8.x4.shared.b16 {%0,%1,%2,%3}, [%4];"
        : "=r"(r[0]), "=r"(r[1]), "=r"(r[2]), "=r"(r[3]) : "r"(addr));
}
__device__ __forceinline__ void mma16816(float* c, const uint32_t* a, uint32_t b0, uint32_t b1) {
    asm volatile("mma.sync.aligned.m16n8k16.row.col.f32.bf16.bf16.f32 "
        "{%0,%1,%2,%3}, {%4,%5,%6,%7}, {%8,%9}, {%0,%1,%2,%3};"
        : "+f"(c[0]), "+f"(c[1]), "+f"(c[2]), "+f"(c[3])
        : "r"(a[0]), "r"(a[1]), "r"(a[2]), "r"(a[3]), "r"(b0), "r"(b1));
}

// ---------------- elementwise kernels ----------------
#define N4_WIN  (2*DI_*DM_/4)
#define N4_WXP  (DBC_*DI_/4)
#define N4_WDT  (DI_*DTR_/4)
#define N4_WOUT (DM_*DI_/4)
#define N4_WHEAD (V_*DM_/4)
#define C1_ (N4_WIN)
#define C2_ (C1_ + N4_WXP)
#define C3_ (C2_ + N4_WDT)
#define C4_ (C3_ + N4_WOUT)
#define C5_ (C4_ + N4_WHEAD)

__global__ void wsplit_all_kernel(const float* __restrict__ win,
                                  const float* __restrict__ wxp,
                                  const float* __restrict__ wdt,
                                  const float* __restrict__ wout,
                                  const float* __restrict__ whead) {
    int i = blockIdx.x * blockDim.x + threadIdx.x;
    if (i >= C5_) return;
    const float* src; int sel; int j;
    if (i < C1_)      { src = win;   sel = P_WIN;   j = i; }
    else if (i < C2_) { src = wxp;   sel = P_WXP;   j = i - C1_; }
    else if (i < C3_) { src = wdt;   sel = P_WDT;   j = i - C2_; }
    else if (i < C4_) { src = wout;  sel = P_WOUT;  j = i - C3_; }
    else              { src = whead; sel = P_WHEAD; j = i - C4_; }
    __nv_bfloat16 *dh, *dl; bpair(sel, dh, dl);
    float4 v = reinterpret_cast<const float4*>(src)[j];
    __nv_bfloat16 h0, l0, h1, l1, h2, l2, h3, l3;
    split1(v.x, h0, l0); split1(v.y, h1, l1);
    split1(v.z, h2, l2); split1(v.w, h3, l3);
    reinterpret_cast<__nv_bfloat162*>(dh)[2*j]   = __nv_bfloat162(h0, h1);
    reinterpret_cast<__nv_bfloat162*>(dh)[2*j+1] = __nv_bfloat162(h2, h3);
    reinterpret_cast<__nv_bfloat162*>(dl)[2*j]   = __nv_bfloat162(l0, l1);
    reinterpret_cast<__nv_bfloat162*>(dl)[2*j+1] = __nv_bfloat162(l2, l3);
}

__global__ void gather_split_kernel(const int* __restrict__ tokens,
                                    const float* __restrict__ embed) {
    int i = blockIdx.x * blockDim.x + threadIdx.x;   // over T_*DM_/4
    int t = i >> 8, j = i & 255;
    int tok = tokens[t];
    float4 v = reinterpret_cast<const float4*>(embed)[tok * 256 + j];
    __nv_bfloat16 h0, l0, h1, l1, h2, l2, h3, l3;
    split1(v.x, h0, l0); split1(v.y, h1, l1);
    split1(v.z, h2, l2); split1(v.w, h3, l3);
    reinterpret_cast<__nv_bfloat162*>(g_aemb_h)[2*i]   = __nv_bfloat162(h0, h1);
    reinterpret_cast<__nv_bfloat162*>(g_aemb_h)[2*i+1] = __nv_bfloat162(h2, h3);
    reinterpret_cast<__nv_bfloat162*>(g_aemb_l)[2*i]   = __nv_bfloat162(l0, l1);
    reinterpret_cast<__nv_bfloat162*>(g_aemb_l)[2*i+1] = __nv_bfloat162(l2, l3);
}

__global__ void zero_dbc_kernel() {
    int i = blockIdx.x * blockDim.x + threadIdx.x;   // T_*DBC_/4
    reinterpret_cast<float4*>(g_dbc)[i] = make_float4(0.f, 0.f, 0.f, 0.f);
}

__global__ void split_dt_kernel() {
    int i = blockIdx.x * blockDim.x + threadIdx.x;   // over T_*16
    if (i >= T_ * 16) return;
    int t = i >> 4, c = (i & 15) * 4;
    float4 v = *reinterpret_cast<const float4*>(&g_dbc[(size_t)t * DBC_ + c]);
    __nv_bfloat16 h0, l0, h1, l1, h2, l2, h3, l3;
    split1(v.x, h0, l0); split1(v.y, h1, l1);
    split1(v.z, h2, l2); split1(v.w, h3, l3);
    size_t o = ((size_t)t * DTR_ + c) >> 1;
    reinterpret_cast<__nv_bfloat162*>(g_adt_h)[o]   = __nv_bfloat162(h0, h1);
    reinterpret_cast<__nv_bfloat162*>(g_adt_h)[o+1] = __nv_bfloat162(h2, h3);
    reinterpret_cast<__nv_bfloat162*>(g_adt_l)[o]   = __nv_bfloat162(l0, l1);
    reinterpret_cast<__nv_bfloat162*>(g_adt_l)[o+1] = __nv_bfloat162(l2, l3);
}

__global__ void conv_silu_kernel(const float* __restrict__ cw,
                                 const float* __restrict__ cb) {
    int i = blockIdx.x * blockDim.x + threadIdx.x;   // over T_*DI_
    int c = i & (DI_ - 1);
    int t = i >> 11;
    int l = t & (L_ - 1);
    float acc = cb[c];
#pragma unroll
    for (int k = 0; k < DC_; k++) {
        int ll = l - (DC_ - 1) + k;
        if (ll >= 0)
            acc = fmaf(cw[c * DC_ + k], g_xz[(size_t)(t - (DC_ - 1) + k) * (2 * DI_) + c], acc);
    }
    float v = siluf(acc);
    g_x[i] = v;
    __nv_bfloat16 h, lo; split1(v, h, lo);
    g_ax_h[i] = h; g_ax_l[i] = lo;
}

__global__ void scan_kernel(const float* __restrict__ A_log) {
    int s  = threadIdx.x & 15;
    int dl = threadIdx.x >> 4;
    int d  = blockIdx.x * 32 + dl;
    int b  = blockIdx.y;
    float a = -__expf(A_log[d * DS_ + s]);
    float h = 0.f;
    int t0 = b * L_;
    const float* dtp = g_dt  + (size_t)t0 * DI_ + d;
    const float* up  = g_x   + (size_t)t0 * DI_ + d;
    const float* bp  = g_dbc + (size_t)t0 * DBC_ + DTR_ + s;
    const float* cp  = bp + DS_;
    float*       yp  = g_y   + (size_t)t0 * DI_ + d;
    for (int l = 0; l < L_; l++) {
        float dtv = *dtp, uv = *up, Bv = *bp, Cv = *cp;
        float dA = __expf(dtv * a);
        h = fmaf(dA, h, dtv * Bv * uv);
        float p = h * Cv;
        p += __shfl_xor_sync(0xffffffffu, p, 1);
        p += __shfl_xor_sync(0xffffffffu, p, 2);
        p += __shfl_xor_sync(0xffffffffu, p, 4);
        p += __shfl_xor_sync(0xffffffffu, p, 8);
        if (s == 0) *yp = p;
        dtp += DI_; up += DI_; bp += DBC_; cp += DBC_; yp += DI_;
    }
}

__global__ void gate_split_kernel(const float* __restrict__ Dv) {
    int i = blockIdx.x * blockDim.x + threadIdx.x;   // over T_*DI_/2
    int e0 = 2 * i;
    int d = e0 & (DI_ - 1);
    int t = e0 >> 11;
    float2 y = *reinterpret_cast<const float2*>(&g_y[e0]);
    float2 x = *reinterpret_cast<const float2*>(&g_x[e0]);
    float2 z = *reinterpret_cast<const float2*>(&g_xz[(size_t)t * (2 * DI_) + DI_ + d]);
    float v0 = (y.x + x.x * Dv[d])     * siluf(z.x);
    float v1 = (y.y + x.y * Dv[d + 1]) * siluf(z.y);
    __nv_bfloat16 h0, l0, h1, l1;
    split1(v0, h0, l0); split1(v1, h1, l1);
    reinterpret_cast<__nv_bfloat162*>(g_ay_h)[i] = __nv_bfloat162(h0, h1);
    reinterpret_cast<__nv_bfloat162*>(g_ay_l)[i] = __nv_bfloat162(l0, l1);
}

// ---------------- HMMA split-bf16 GEMM (mma.sync m16n8k16) ----------------
// C[M,N] = (Ah+Al)[M,K] @ ((Bh+Bl)[N,K])^T, 3-product split, fp32 accum.
// Tile 128x128xBK32, 256 threads = 8 warps (4 m x 2 n), warp tile 32x64.
// XOR-swizzled smem (64B rows). 3 stages x 32KB = 96KB -> 2 CTAs/SM.
// Mainloop: ONE barrier per kt (wait -> sync -> compute -> load(st+2) -> commit).
// Safe with 3 stages: load target (kt+2)%3 differs from stages kt%3 / (kt+1)%3
// that any warp between consecutive barriers can read.
// All ldmatrix swizzled offsets hoisted out of the kt loop.
#define ARR_B   8192                       // 128 rows * 64B per array
#define STAGE_B (4 * ARR_B)                // 32768 bytes
#define SMEM_MMA (3 * STAGE_B)             // 98304 bytes

template<bool GX>
__global__ __launch_bounds__(256, 2)
void gemm_mma(int a_sel, int b_sel, int c_sel, float* __restrict__ C_ext,
              int pair_sel, const float* __restrict__ bias,
              int M, int N, int K, int KC, int epi) {
    extern __shared__ __nv_bfloat16 sm[];
    __nv_bfloat16 *Ah, *Al, *Bh, *Bl;
    bpair(a_sel, Ah, Al);
    bpair(b_sel, Bh, Bl);
    float* __restrict__ C = buf_ptr_mut(c_sel, C_ext);
    __nv_bfloat16 *Oh = nullptr, *Ol = nullptr;
    if (pair_sel != P_NONE) bpair(pair_sel, Oh, Ol);

    const int tid  = threadIdx.x;
    const int wid  = tid >> 5, lane = tid & 31;
    const int bm   = blockIdx.x * 128;
    const int bn   = blockIdx.y * 128;
    const int kbase = blockIdx.z * KC;
    const int wm   = wid & 3;                   // 4 m-warps of 32 rows
    const int wn   = wid >> 2;                  // 2 n-warps of 64 cols
    const int KT   = KC >> 5;

    const uint32_t sb0 = smem_u32(sm);

    auto load_stage = [&](int st, int kt) {
        const int k0 = kbase + kt * 32;
        const uint32_t sb = sb0 + st * STAGE_B;
#pragma unroll
        for (int ii = 0; ii < 8; ii++) {
            int i   = tid + ii * 256;
            int arr = i >> 9;
            int r   = (i >> 2) & 127;
            int cc  = i & 3;
            const __nv_bfloat16* src = (arr == 0) ? Ah : (arr == 1) ? Al
                                     : (arr == 2) ? Bh : Bl;
            uint32_t dst = sb + (uint32_t)(arr * ARR_B + r * 64
                                           + ((cc ^ ((r >> 1) & 3)) << 4));
            if (GX && arr >= 2) {
                int grow = bn + r;
                uint32_t ok = (grow < N) ? 16u : 0u;
                int ge = (grow < N) ? grow : 0;
                cp16z(dst, src + (size_t)ge * K + k0 + cc * 8, ok);
            } else {
                int grow = (arr < 2 ? bm : bn) + r;
                cp16(dst, src + (size_t)grow * K + k0 + cc * 8);
            }
        }
    };

    float acc[2][8][4];
#pragma unroll
    for (int i = 0; i < 2; i++)
#pragma unroll
        for (int j = 0; j < 8; j++)
#pragma unroll
            for (int k = 0; k < 4; k++) acc[i][j][k] = 0.f;

    // prologue: stages 0,1
    load_stage(0, 0);
    asm volatile("cp.async.commit_group;" ::: "memory");
    if (KT > 1) load_stage(1, 1);
    asm volatile("cp.async.commit_group;" ::: "memory");

    // hoisted ldmatrix offsets (within-stage byte offsets)
    //   A: [k16][mt], arrays Ah at +0, Al at +ARR_B
    //   B: [k16][nt2], arrays Bh at +2*ARR_B, Bl at +3*ARR_B
    const int a_r = (lane & 15);
    const int ca  = (lane >> 4);
    const int b_r = ((lane >> 3) & 1) * 8 + (lane & 7);
    const int cb  = (lane >> 4);
    uint32_t offA[2][2], offB[2][4];
#pragma unroll
    for (int k16 = 0; k16 < 2; k16++) {
#pragma unroll
        for (int mt = 0; mt < 2; mt++) {
            int row = wm * 32 + mt * 16 + a_r;
            int cc  = 2 * k16 + ca;
            offA[k16][mt] = (uint32_t)(row * 64 + ((cc ^ ((row >> 1) & 3)) << 4));
        }
#pragma unroll
        for (int nt2 = 0; nt2 < 4; nt2++) {
            int row = wn * 64 + nt2 * 16 + b_r;
            int cc  = 2 * k16 + cb;
            offB[k16][nt2] = (uint32_t)(row * 64 + ((cc ^ ((row >> 1) & 3)) << 4));
        }
    }

    int st = 0;
    for (int kt = 0; kt < KT; kt++) {
        asm volatile("cp.async.wait_group 1;" ::: "memory");
        __syncthreads();
        const uint32_t sb = sb0 + st * STAGE_B;

#pragma unroll
        for (int k16 = 0; k16 < 2; k16++) {
            uint32_t ah[2][4], al[2][4];
#pragma unroll
            for (int mt = 0; mt < 2; mt++) {
                uint32_t off = offA[k16][mt];
                ldsm4(ah[mt], sb + off);
                ldsm4(al[mt], sb + ARR_B + off);
            }
#pragma unroll
            for (int nt2 = 0; nt2 < 4; nt2++) {
                uint32_t off = offB[k16][nt2];
                uint32_t bh[4], bl[4];
                ldsm4(bh, sb + 2 * ARR_B + off);
                ldsm4(bl, sb + 3 * ARR_B + off);
#pragma unroll
                for (int mt = 0; mt < 2; mt++) {
                    float* c0 = acc[mt][nt2 * 2];
                    float* c1 = acc[mt][nt2 * 2 + 1];
                    mma16816(c0, ah[mt], bh[0], bh[2]);
                    mma16816(c0, ah[mt], bl[0], bl[2]);
                    mma16816(c0, al[mt], bh[0], bh[2]);
                    mma16816(c1, ah[mt], bh[1], bh[3]);
                    mma16816(c1, ah[mt], bl[1], bl[3]);
                    mma16816(c1, al[mt], bh[1], bh[3]);
                }
            }
        }

        // load two stages ahead AFTER compute; no trailing barrier needed
        if (kt + 2 < KT) {
            int st2 = st + 2; if (st2 >= 3) st2 -= 3;
            load_stage(st2, kt + 2);
        }
        asm volatile("cp.async.commit_group;" ::: "memory");
        if (++st == 3) st = 0;
    }

    // epilogue
    const int er = bm + wm * 32 + (lane >> 2);
    const int ec = bn + wn * 64 + (lane & 3) * 2;
#pragma unroll
    for (int mt = 0; mt < 2; mt++) {
#pragma unroll
        for (int nt = 0; nt < 8; nt++) {
            int col = ec + nt * 8;
            if (GX) {
                if (col >= N) continue;
#pragma unroll
                for (int half = 0; half < 2; half++) {
                    int row = er + mt * 16 + half * 8;
                    atomicAdd(&C[(size_t)row * N + col],     acc[mt][nt][half * 2 + 0]);
                    atomicAdd(&C[(size_t)row * N + col + 1], acc[mt][nt][half * 2 + 1]);
                }
            } else {
                float b0 = 0.f, b1 = 0.f;
                if (epi >= 1) { b0 = bias[col]; b1 = bias[col + 1]; }
#pragma unroll
                for (int half = 0; half < 2; half++) {
                    int row = er + mt * 16 + half * 8;
                    float v0 = acc[mt][nt][half * 2 + 0] + b0;
                    float v1 = acc[mt][nt][half * 2 + 1] + b1;
                    if (epi == 2) { v0 = softplusf(v0); v1 = softplusf(v1); }
                    if (pair_sel != P_NONE) {
                        __nv_bfloat16 h0, l0, h1, l1;
                        split1(v0, h0, l0); split1(v1, h1, l1);
                        size_t o = ((size_t)row * N + col) >> 1;
                        reinterpret_cast<__nv_bfloat162*>(Oh)[o] = __nv_bfloat162(h0, h1);
                        reinterpret_cast<__nv_bfloat162*>(Ol)[o] = __nv_bfloat162(l0, l1);
                    } else {
                        *reinterpret_cast<float2*>(&C[(size_t)row * N + col]) =
                            make_float2(v0, v1);
                    }
                }
            }
        }
    }
}

// ---------------- launch ----------------
extern "C" void kernel_launch(void* const* d_in, const int* in_sizes, int n_in,
                              void* d_out, int out_size) {
    const int*   tokens     = (const int*)  d_in[0];
    const float* embed      = (const float*)d_in[1];
    const float* in_proj_w  = (const float*)d_in[2];
    const float* conv_w     = (const float*)d_in[3];
    const float* conv_b     = (const float*)d_in[4];
    const float* x_proj_w   = (const float*)d_in[5];
    const float* dt_proj_w  = (const float*)d_in[6];
    const float* dt_proj_b  = (const float*)d_in[7];
    const float* A_log      = (const float*)d_in[8];
    const float* Dv         = (const float*)d_in[9];
    const float* out_proj_w = (const float*)d_in[10];
    const float* head_w     = (const float*)d_in[11];
    const float* head_b     = (const float*)d_in[12];
    float* out = (float*)d_out;

    cudaFuncSetAttribute(gemm_mma<false>, cudaFuncAttributeMaxDynamicSharedMemorySize, SMEM_MMA);
    cudaFuncSetAttribute(gemm_mma<true>,  cudaFuncAttributeMaxDynamicSharedMemorySize, SMEM_MMA);

    // 1. all weight splits (one launch)
    wsplit_all_kernel<<<(C5_ + 255) / 256, 256>>>(in_proj_w, x_proj_w, dt_proj_w,
                                                  out_proj_w, head_w);

    // 2. embedding gather + split (fused)
    gather_split_kernel<<<(T_ * DM_ / 4) / 256, 256>>>(tokens, embed);

    // 3. zero dbc accumulator (for x_proj split-K atomics)
    zero_dbc_kernel<<<(T_ * DBC_ / 4) / 256, 256>>>();

    // 4. in_proj (HMMA, fast path) -- profiler capture slot
    gemm_mma<false><<<dim3(T_/128, 2*DI_/128), 256, SMEM_MMA>>>(
        P_AEMB, P_WIN, BUF_XZ, nullptr, P_NONE, nullptr, T_, 2*DI_, DM_, DM_, 0);

    // 5. causal conv + SiLU + split (fused)
    conv_silu_kernel<<<(T_ * DI_) / 256, 256>>>(conv_w, conv_b);

    // 6. x_proj (HMMA guarded, split-K=8): dbc += x @ x_proj_w^T
    gemm_mma<true><<<dim3(T_/128, 1, 8), 256, SMEM_MMA>>>(
        P_AX, P_WXP, BUF_DBC, nullptr, P_NONE, nullptr, T_, DBC_, DI_, DI_/8, 0);

    // 7. dt input split
    split_dt_kernel<<<(T_*16 + 255)/256, 256>>>();

    // 8. dt (HMMA): dt = softplus(dbc[:, :64] @ dt_proj_w^T + b)
    gemm_mma<false><<<dim3(T_/128, DI_/128), 256, SMEM_MMA>>>(
        P_ADT, P_WDT, BUF_DT, nullptr, P_NONE, dt_proj_b, T_, DI_, DTR_, DTR_, 2);

    // 9. selective scan
    scan_kernel<<<dim3(DI_/32, B_), 512>>>(A_log);

    // 10. gating + split (fused)
    gate_split_kernel<<<(T_ * DI_ / 2) / 256, 256>>>(Dv);

    // 11. out_proj (HMMA, split-pair epilogue): ay2 = split(y @ out_proj_w^T)
    gemm_mma<false><<<dim3(T_/128, DM_/128), 256, SMEM_MMA>>>(
        P_AY, P_WOUT, BUF_EXT, nullptr, P_AY2, nullptr, T_, DM_, DI_, DI_, 0);

    // 12. head (HMMA): out = y2 @ head_w^T + head_b
    gemm_mma<false><<<dim3(T_/128, V_/128), 256, SMEM_MMA>>>(
        P_AY2, P_WHEAD, BUF_EXT, out, P_NONE, head_b, T_, V_, DM_, DM_, 1);
}

// round 16
// speedup vs baseline: 1.7030x; 1.7030x over previous
#include <cuda_runtime.h>
#include <cuda_bf16.h>
#include <cstdint>
#include <math.h>

// Problem constants
#define B_   2
#define L_   2048
#define T_   4096        // B_*L_
#define DM_  1024
#define DI_  2048
#define DS_  16
#define DC_  4
#define DTR_ 64
#define V_   32000
#define DBC_ 96          // DTR + 2*DS

// ---------------- fp32 scratch ----------------
__device__ float g_xz [T_ * 2 * DI_];    // x | z
__device__ float g_x  [T_ * DI_];
__device__ float g_dbc[T_ * DBC_];
__device__ float g_dt [T_ * DI_];
__device__ float g_y  [T_ * DI_];

// ---------------- bf16 split scratch (hi/lo) ----------------
__device__ __nv_bfloat16 g_aemb_h[T_ * DM_],  g_aemb_l[T_ * DM_];
__device__ __nv_bfloat16 g_ax_h  [T_ * DI_],  g_ax_l  [T_ * DI_];
__device__ __nv_bfloat16 g_adt_h [T_ * DTR_], g_adt_l [T_ * DTR_];
__device__ __nv_bfloat16 g_ay_h  [T_ * DI_],  g_ay_l  [T_ * DI_];
__device__ __nv_bfloat16 g_ay2_h [T_ * DM_],  g_ay2_l [T_ * DM_];
__device__ __nv_bfloat16 g_win_h [2*DI_*DM_], g_win_l [2*DI_*DM_];
__device__ __nv_bfloat16 g_wxp_h [DBC_*DI_],  g_wxp_l [DBC_*DI_];
__device__ __nv_bfloat16 g_wdt_h [DI_*DTR_],  g_wdt_l [DI_*DTR_];
__device__ __nv_bfloat16 g_wout_h[DM_*DI_],   g_wout_l[DM_*DI_];
__device__ __nv_bfloat16 g_whead_h[(size_t)V_*DM_], g_whead_l[(size_t)V_*DM_];

// ---------------- selectors ----------------
enum Buf   { BUF_XZ = 0, BUF_X, BUF_DBC, BUF_DT, BUF_Y, BUF_EXT };
enum BPair { P_AEMB = 0, P_AX, P_ADT, P_AY, P_AY2,
             P_WIN, P_WXP, P_WDT, P_WOUT, P_WHEAD, P_NONE };

__device__ __forceinline__ float* buf_ptr_mut(int sel, float* ext) {
    switch (sel) {
        case BUF_XZ: return g_xz;   case BUF_X:  return g_x;
        case BUF_DBC: return g_dbc; case BUF_DT: return g_dt;
        case BUF_Y:  return g_y;    default:     return ext;
    }
}
__device__ __forceinline__ void bpair(int sel, __nv_bfloat16*& h, __nv_bfloat16*& l) {
    switch (sel) {
        case P_AEMB: h = g_aemb_h;  l = g_aemb_l;  break;
        case P_AX:   h = g_ax_h;    l = g_ax_l;    break;
        case P_ADT:  h = g_adt_h;   l = g_adt_l;   break;
        case P_AY:   h = g_ay_h;    l = g_ay_l;    break;
        case P_AY2:  h = g_ay2_h;   l = g_ay2_l;   break;
        case P_WIN:  h = g_win_h;   l = g_win_l;   break;
        case P_WXP:  h = g_wxp_h;   l = g_wxp_l;   break;
        case P_WDT:  h = g_wdt_h;   l = g_wdt_l;   break;
        case P_WOUT: h = g_wout_h;  l = g_wout_l;  break;
        case P_WHEAD: h = g_whead_h; l = g_whead_l; break;
        default:     h = nullptr;   l = nullptr;   break;
    }
}

// ---------------- math helpers ----------------
__device__ __forceinline__ float softplusf(float x) {
    return fmaxf(x, 0.f) + log1pf(__expf(-fabsf(x)));
}
__device__ __forceinline__ float siluf(float x) {
    return x / (1.f + __expf(-x));
}
__device__ __forceinline__ void split1(float x, __nv_bfloat16& h, __nv_bfloat16& l) {
    h = __float2bfloat16(x);
    l = __float2bfloat16(x - __bfloat162float(h));
}
__device__ __forceinline__ uint32_t smem_u32(const void* p) {
    uint32_t a;
    asm("{ .reg .u64 t; cvta.to.shared.u64 t, %1; cvt.u32.u64 %0, t; }" : "=r"(a) : "l"(p));
    return a;
}
__device__ __forceinline__ void cp16(uint32_t saddr, const void* g) {
    asm volatile("cp.async.cg.shared.global [%0], [%1], 16;" :: "r"(saddr), "l"(g));
}
__device__ __forceinline__ void cp16z(uint32_t saddr, const void* g, uint32_t srcsz) {
    asm volatile("cp.async.cg.shared.global [%0], [%1], 16, %2;"
                 :: "r"(saddr), "l"(g), "r"(srcsz));
}
__device__ __forceinline__ void ldsm4(uint32_t* r, uint32_t addr) {
    asm volatile("ldmatrix.sync.aligned.m8n8.x4.shared.b16 {%0,%1,%2,%3}, [%4];"
        : "=r"(r[0]), "=r"(r[1]), "=r"(r[2]), "=r"(r[3]) : "r"(addr));
}
__device__ __forceinline__ void mma16816(float* c, const uint32_t* a, uint32_t b0, uint32_t b1) {
    asm volatile("mma.sync.aligned.m16n8k16.row.col.f32.bf16.bf16.f32 "
        "{%0,%1,%2,%3}, {%4,%5,%6,%7}, {%8,%9}, {%0,%1,%2,%3};"
        : "+f"(c[0]), "+f"(c[1]), "+f"(c[2]), "+f"(c[3])
        : "r"(a[0]), "r"(a[1]), "r"(a[2]), "r"(a[3]), "r"(b0), "r"(b1));
}

// ---------------- elementwise kernels ----------------
#define N4_WIN  (2*DI_*DM_/4)
#define N4_WXP  (DBC_*DI_/4)
#define N4_WDT  (DI_*DTR_/4)
#define N4_WOUT (DM_*DI_/4)
#define N4_WHEAD (V_*DM_/4)
#define C1_ (N4_WIN)
#define C2_ (C1_ + N4_WXP)
#define C3_ (C2_ + N4_WDT)
#define C4_ (C3_ + N4_WOUT)
#define C5_ (C4_ + N4_WHEAD)

__global__ void wsplit_all_kernel(const float* __restrict__ win,
                                  const float* __restrict__ wxp,
                                  const float* __restrict__ wdt,
                                  const float* __restrict__ wout,
                                  const float* __restrict__ whead) {
    int i = blockIdx.x * blockDim.x + threadIdx.x;
    if (i >= C5_) return;
    const float* src; int sel; int j;
    if (i < C1_)      { src = win;   sel = P_WIN;   j = i; }
    else if (i < C2_) { src = wxp;   sel = P_WXP;   j = i - C1_; }
    else if (i < C3_) { src = wdt;   sel = P_WDT;   j = i - C2_; }
    else if (i < C4_) { src = wout;  sel = P_WOUT;  j = i - C3_; }
    else              { src = whead; sel = P_WHEAD; j = i - C4_; }
    __nv_bfloat16 *dh, *dl; bpair(sel, dh, dl);
    float4 v = reinterpret_cast<const float4*>(src)[j];
    __nv_bfloat16 h0, l0, h1, l1, h2, l2, h3, l3;
    split1(v.x, h0, l0); split1(v.y, h1, l1);
    split1(v.z, h2, l2); split1(v.w, h3, l3);
    reinterpret_cast<__nv_bfloat162*>(dh)[2*j]   = __nv_bfloat162(h0, h1);
    reinterpret_cast<__nv_bfloat162*>(dh)[2*j+1] = __nv_bfloat162(h2, h3);
    reinterpret_cast<__nv_bfloat162*>(dl)[2*j]   = __nv_bfloat162(l0, l1);
    reinterpret_cast<__nv_bfloat162*>(dl)[2*j+1] = __nv_bfloat162(l2, l3);
}

__global__ void gather_split_kernel(const int* __restrict__ tokens,
                                    const float* __restrict__ embed) {
    int i = blockIdx.x * blockDim.x + threadIdx.x;   // over T_*DM_/4
    int t = i >> 8, j = i & 255;
    int tok = tokens[t];
    float4 v = reinterpret_cast<const float4*>(embed)[tok * 256 + j];
    __nv_bfloat16 h0, l0, h1, l1, h2, l2, h3, l3;
    split1(v.x, h0, l0); split1(v.y, h1, l1);
    split1(v.z, h2, l2); split1(v.w, h3, l3);
    reinterpret_cast<__nv_bfloat162*>(g_aemb_h)[2*i]   = __nv_bfloat162(h0, h1);
    reinterpret_cast<__nv_bfloat162*>(g_aemb_h)[2*i+1] = __nv_bfloat162(h2, h3);
    reinterpret_cast<__nv_bfloat162*>(g_aemb_l)[2*i]   = __nv_bfloat162(l0, l1);
    reinterpret_cast<__nv_bfloat162*>(g_aemb_l)[2*i+1] = __nv_bfloat162(l2, l3);
}

__global__ void zero_dbc_kernel() {
    int i = blockIdx.x * blockDim.x + threadIdx.x;   // T_*DBC_/4
    reinterpret_cast<float4*>(g_dbc)[i] = make_float4(0.f, 0.f, 0.f, 0.f);
}

__global__ void split_dt_kernel() {
    int i = blockIdx.x * blockDim.x + threadIdx.x;   // over T_*16
    if (i >= T_ * 16) return;
    int t = i >> 4, c = (i & 15) * 4;
    float4 v = *reinterpret_cast<const float4*>(&g_dbc[(size_t)t * DBC_ + c]);
    __nv_bfloat16 h0, l0, h1, l1, h2, l2, h3, l3;
    split1(v.x, h0, l0); split1(v.y, h1, l1);
    split1(v.z, h2, l2); split1(v.w, h3, l3);
    size_t o = ((size_t)t * DTR_ + c) >> 1;
    reinterpret_cast<__nv_bfloat162*>(g_adt_h)[o]   = __nv_bfloat162(h0, h1);
    reinterpret_cast<__nv_bfloat162*>(g_adt_h)[o+1] = __nv_bfloat162(h2, h3);
    reinterpret_cast<__nv_bfloat162*>(g_adt_l)[o]   = __nv_bfloat162(l0, l1);
    reinterpret_cast<__nv_bfloat162*>(g_adt_l)[o+1] = __nv_bfloat162(l2, l3);
}

__global__ void conv_silu_kernel(const float* __restrict__ cw,
                                 const float* __restrict__ cb) {
    int i = blockIdx.x * blockDim.x + threadIdx.x;   // over T_*DI_
    int c = i & (DI_ - 1);
    int t = i >> 11;
    int l = t & (L_ - 1);
    float acc = cb[c];
#pragma unroll
    for (int k = 0; k < DC_; k++) {
        int ll = l - (DC_ - 1) + k;
        if (ll >= 0)
            acc = fmaf(cw[c * DC_ + k], g_xz[(size_t)(t - (DC_ - 1) + k) * (2 * DI_) + c], acc);
    }
    float v = siluf(acc);
    g_x[i] = v;
    __nv_bfloat16 h, lo; split1(v, h, lo);
    g_ax_h[i] = h; g_ax_l[i] = lo;
}

// selective scan with register prefetch pipeline (depth 4):
// loads for iteration l+4 are issued while computing iteration l, so the
// serial recurrence no longer pays the global-load latency per step.
__global__ void scan_kernel(const float* __restrict__ A_log) {
    int s  = threadIdx.x & 15;
    int dl = threadIdx.x >> 4;
    int d  = blockIdx.x * 32 + dl;
    int b  = blockIdx.y;
    float a = -__expf(A_log[d * DS_ + s]);
    float h = 0.f;
    int t0 = b * L_;
    const float* dtp = g_dt  + (size_t)t0 * DI_ + d;
    const float* up  = g_x   + (size_t)t0 * DI_ + d;
    const float* bp  = g_dbc + (size_t)t0 * DBC_ + DTR_ + s;
    const float* cp  = bp + DS_;
    float*       yp  = g_y   + (size_t)t0 * DI_ + d;

    float pdt[4], pu[4], pB[4], pC[4];
#pragma unroll
    for (int j = 0; j < 4; j++) {
        pdt[j] = dtp[(size_t)j * DI_];
        pu[j]  = up [(size_t)j * DI_];
        pB[j]  = bp [(size_t)j * DBC_];
        pC[j]  = cp [(size_t)j * DBC_];
    }

    for (int l = 0; l < L_; l += 4) {
#pragma unroll
        for (int j = 0; j < 4; j++) {
            float dtv = pdt[j], uv = pu[j], Bv = pB[j], Cv = pC[j];
            // prefetch l+4+j (clamped to stay in-bounds on the last block)
            int lp = l + 4 + j;
            int off = (lp < L_) ? lp : (L_ - 1);
            pdt[j] = dtp[(size_t)off * DI_];
            pu[j]  = up [(size_t)off * DI_];
            pB[j]  = bp [(size_t)off * DBC_];
            pC[j]  = cp [(size_t)off * DBC_];

            float dA = __expf(dtv * a);
            h = fmaf(dA, h, dtv * Bv * uv);
            float p = h * Cv;
            p += __shfl_xor_sync(0xffffffffu, p, 1);
            p += __shfl_xor_sync(0xffffffffu, p, 2);
            p += __shfl_xor_sync(0xffffffffu, p, 4);
            p += __shfl_xor_sync(0xffffffffu, p, 8);
            if (s == 0) yp[(size_t)(l + j) * DI_] = p;
        }
    }
}

__global__ void gate_split_kernel(const float* __restrict__ Dv) {
    int i = blockIdx.x * blockDim.x + threadIdx.x;   // over T_*DI_/2
    int e0 = 2 * i;
    int d = e0 & (DI_ - 1);
    int t = e0 >> 11;
    float2 y = *reinterpret_cast<const float2*>(&g_y[e0]);
    float2 x = *reinterpret_cast<const float2*>(&g_x[e0]);
    float2 z = *reinterpret_cast<const float2*>(&g_xz[(size_t)t * (2 * DI_) + DI_ + d]);
    float v0 = (y.x + x.x * Dv[d])     * siluf(z.x);
    float v1 = (y.y + x.y * Dv[d + 1]) * siluf(z.y);
    __nv_bfloat16 h0, l0, h1, l1;
    split1(v0, h0, l0); split1(v1, h1, l1);
    reinterpret_cast<__nv_bfloat162*>(g_ay_h)[i] = __nv_bfloat162(h0, h1);
    reinterpret_cast<__nv_bfloat162*>(g_ay_l)[i] = __nv_bfloat162(l0, l1);
}

// ---------------- HMMA split-bf16 GEMM (mma.sync m16n8k16) ----------------
// R12-proven mainloop: two barriers per kt, load(st+2) issued BEFORE compute
// (2 compute phases of cp.async lead time -- do not reorder; R13 showed -46%).
// Tile 128x128xBK32, 8 warps (4m x 2n), warp tile 32x64, XOR-swizzled smem,
// 3 stages x 32KB = 96KB -> 2 CTAs/SM.
#define ARR_B   8192                       // 128 rows * 64B per array
#define STAGE_B (4 * ARR_B)                // 32768 bytes
#define SMEM_MMA (3 * STAGE_B)             // 98304 bytes

template<bool GX>
__global__ __launch_bounds__(256, 2)
void gemm_mma(int a_sel, int b_sel, int c_sel, float* __restrict__ C_ext,
              int pair_sel, const float* __restrict__ bias,
              int M, int N, int K, int KC, int epi) {
    extern __shared__ __nv_bfloat16 sm[];
    __nv_bfloat16 *Ah, *Al, *Bh, *Bl;
    bpair(a_sel, Ah, Al);
    bpair(b_sel, Bh, Bl);
    float* __restrict__ C = buf_ptr_mut(c_sel, C_ext);
    __nv_bfloat16 *Oh = nullptr, *Ol = nullptr;
    if (pair_sel != P_NONE) bpair(pair_sel, Oh, Ol);

    const int tid  = threadIdx.x;
    const int wid  = tid >> 5, lane = tid & 31;
    const int bm   = blockIdx.x * 128;
    const int bn   = blockIdx.y * 128;
    const int kbase = blockIdx.z * KC;
    const int wm   = wid & 3;                   // 4 m-warps of 32 rows
    const int wn   = wid >> 2;                  // 2 n-warps of 64 cols
    const int KT   = KC >> 5;

    const uint32_t sb0 = smem_u32(sm);

    auto load_stage = [&](int st, int kt) {
        const int k0 = kbase + kt * 32;
        const uint32_t sb = sb0 + st * STAGE_B;
#pragma unroll
        for (int ii = 0; ii < 8; ii++) {
            int i   = tid + ii * 256;
            int arr = i >> 9;
            int r   = (i >> 2) & 127;
            int cc  = i & 3;
            const __nv_bfloat16* src = (arr == 0) ? Ah : (arr == 1) ? Al
                                     : (arr == 2) ? Bh : Bl;
            uint32_t dst = sb + (uint32_t)(arr * ARR_B + r * 64
                                           + ((cc ^ ((r >> 1) & 3)) << 4));
            if (GX && arr >= 2) {
                int grow = bn + r;
                uint32_t ok = (grow < N) ? 16u : 0u;
                int ge = (grow < N) ? grow : 0;
                cp16z(dst, src + (size_t)ge * K + k0 + cc * 8, ok);
            } else {
                int grow = (arr < 2 ? bm : bn) + r;
                cp16(dst, src + (size_t)grow * K + k0 + cc * 8);
            }
        }
    };

    float acc[2][8][4];
#pragma unroll
    for (int i = 0; i < 2; i++)
#pragma unroll
        for (int j = 0; j < 8; j++)
#pragma unroll
            for (int k = 0; k < 4; k++) acc[i][j][k] = 0.f;

    // prologue: stages 0,1
    load_stage(0, 0);
    asm volatile("cp.async.commit_group;" ::: "memory");
    if (KT > 1) load_stage(1, 1);
    asm volatile("cp.async.commit_group;" ::: "memory");

    const int a_r = (lane & 15);
    const int ca  = (lane >> 4);
    const int b_r = ((lane >> 3) & 1) * 8 + (lane & 7);
    const int cb  = (lane >> 4);

    int st = 0;
    for (int kt = 0; kt < KT; kt++) {
        asm volatile("cp.async.wait_group 1;" ::: "memory");
        __syncthreads();
        // refill two stages ahead BEFORE compute (overlaps this iter's MMAs)
        if (kt + 2 < KT) {
            int st2 = st + 2; if (st2 >= 3) st2 -= 3;
            load_stage(st2, kt + 2);
        }
        asm volatile("cp.async.commit_group;" ::: "memory");

        const uint32_t sb = sb0 + st * STAGE_B;
#pragma unroll
        for (int k16 = 0; k16 < 2; k16++) {
            uint32_t ah[2][4], al[2][4];
#pragma unroll
            for (int mt = 0; mt < 2; mt++) {
                int row = wm * 32 + mt * 16 + a_r;
                int cc  = 2 * k16 + ca;
                uint32_t off = (uint32_t)(row * 64 + ((cc ^ ((row >> 1) & 3)) << 4));
                ldsm4(ah[mt], sb + off);
                ldsm4(al[mt], sb + ARR_B + off);
            }
#pragma unroll
            for (int nt2 = 0; nt2 < 4; nt2++) {
                int row = wn * 64 + nt2 * 16 + b_r;
                int cc  = 2 * k16 + cb;
                uint32_t off = (uint32_t)(row * 64 + ((cc ^ ((row >> 1) & 3)) << 4));
                uint32_t bh[4], bl[4];
                ldsm4(bh, sb + 2 * ARR_B + off);
                ldsm4(bl, sb + 3 * ARR_B + off);
#pragma unroll
                for (int mt = 0; mt < 2; mt++) {
                    float* c0 = acc[mt][nt2 * 2];
                    float* c1 = acc[mt][nt2 * 2 + 1];
                    mma16816(c0, ah[mt], bh[0], bh[2]);
                    mma16816(c0, ah[mt], bl[0], bl[2]);
                    mma16816(c0, al[mt], bh[0], bh[2]);
                    mma16816(c1, ah[mt], bh[1], bh[3]);
                    mma16816(c1, ah[mt], bl[1], bl[3]);
                    mma16816(c1, al[mt], bh[1], bh[3]);
                }
            }
        }
        __syncthreads();
        if (++st == 3) st = 0;
    }

    // epilogue
    const int er = bm + wm * 32 + (lane >> 2);
    const int ec = bn + wn * 64 + (lane & 3) * 2;
#pragma unroll
    for (int mt = 0; mt < 2; mt++) {
#pragma unroll
        for (int nt = 0; nt < 8; nt++) {
            int col = ec + nt * 8;
            if (GX) {
                if (col >= N) continue;
#pragma unroll
                for (int half = 0; half < 2; half++) {
                    int row = er + mt * 16 + half * 8;
                    atomicAdd(&C[(size_t)row * N + col],     acc[mt][nt][half * 2 + 0]);
                    atomicAdd(&C[(size_t)row * N + col + 1], acc[mt][nt][half * 2 + 1]);
                }
            } else {
                float b0 = 0.f, b1 = 0.f;
                if (epi >= 1) { b0 = bias[col]; b1 = bias[col + 1]; }
#pragma unroll
                for (int half = 0; half < 2; half++) {
                    int row = er + mt * 16 + half * 8;
                    float v0 = acc[mt][nt][half * 2 + 0] + b0;
                    float v1 = acc[mt][nt][half * 2 + 1] + b1;
                    if (epi == 2) { v0 = softplusf(v0); v1 = softplusf(v1); }
                    if (pair_sel != P_NONE) {
                        __nv_bfloat16 h0, l0, h1, l1;
                        split1(v0, h0, l0); split1(v1, h1, l1);
                        size_t o = ((size_t)row * N + col) >> 1;
                        reinterpret_cast<__nv_bfloat162*>(Oh)[o] = __nv_bfloat162(h0, h1);
                        reinterpret_cast<__nv_bfloat162*>(Ol)[o] = __nv_bfloat162(l0, l1);
                    } else {
                        *reinterpret_cast<float2*>(&C[(size_t)row * N + col]) =
                            make_float2(v0, v1);
                    }
                }
            }
        }
    }
}

// ---------------- launch ----------------
extern "C" void kernel_launch(void* const* d_in, const int* in_sizes, int n_in,
                              void* d_out, int out_size) {
    const int*   tokens     = (const int*)  d_in[0];
    const float* embed      = (const float*)d_in[1];
    const float* in_proj_w  = (const float*)d_in[2];
    const float* conv_w     = (const float*)d_in[3];
    const float* conv_b     = (const float*)d_in[4];
    const float* x_proj_w   = (const float*)d_in[5];
    const float* dt_proj_w  = (const float*)d_in[6];
    const float* dt_proj_b  = (const float*)d_in[7];
    const float* A_log      = (const float*)d_in[8];
    const float* Dv         = (const float*)d_in[9];
    const float* out_proj_w = (const float*)d_in[10];
    const float* head_w     = (const float*)d_in[11];
    const float* head_b     = (const float*)d_in[12];
    float* out = (float*)d_out;

    cudaFuncSetAttribute(gemm_mma<false>, cudaFuncAttributeMaxDynamicSharedMemorySize, SMEM_MMA);
    cudaFuncSetAttribute(gemm_mma<true>,  cudaFuncAttributeMaxDynamicSharedMemorySize, SMEM_MMA);

    // 1. all weight splits (one launch)
    wsplit_all_kernel<<<(C5_ + 255) / 256, 256>>>(in_proj_w, x_proj_w, dt_proj_w,
                                                  out_proj_w, head_w);

    // 2. embedding gather + split (fused)
    gather_split_kernel<<<(T_ * DM_ / 4) / 256, 256>>>(tokens, embed);

    // 3. zero dbc accumulator (for x_proj split-K atomics)
    zero_dbc_kernel<<<(T_ * DBC_ / 4) / 256, 256>>>();

    // 4. in_proj (HMMA, fast path) -- profiler capture slot
    gemm_mma<false><<<dim3(T_/128, 2*DI_/128), 256, SMEM_MMA>>>(
        P_AEMB, P_WIN, BUF_XZ, nullptr, P_NONE, nullptr, T_, 2*DI_, DM_, DM_, 0);

    // 5. causal conv + SiLU + split (fused)
    conv_silu_kernel<<<(T_ * DI_) / 256, 256>>>(conv_w, conv_b);

    // 6. x_proj (HMMA guarded, split-K=8): dbc += x @ x_proj_w^T
    gemm_mma<true><<<dim3(T_/128, 1, 8), 256, SMEM_MMA>>>(
        P_AX, P_WXP, BUF_DBC, nullptr, P_NONE, nullptr, T_, DBC_, DI_, DI_/8, 0);

    // 7. dt input split
    split_dt_kernel<<<(T_*16 + 255)/256, 256>>>();

    // 8. dt (HMMA): dt = softplus(dbc[:, :64] @ dt_proj_w^T + b)
    gemm_mma<false><<<dim3(T_/128, DI_/128), 256, SMEM_MMA>>>(
        P_ADT, P_WDT, BUF_DT, nullptr, P_NONE, dt_proj_b, T_, DI_, DTR_, DTR_, 2);

    // 9. selective scan (prefetch depth 4)
    scan_kernel<<<dim3(DI_/32, B_), 512>>>(A_log);

    // 10. gating + split (fused)
    gate_split_kernel<<<(T_ * DI_ / 2) / 256, 256>>>(Dv);

    // 11. out_proj (HMMA, split-pair epilogue): ay2 = split(y @ out_proj_w^T)
    gemm_mma<false><<<dim3(T_/128, DM_/128), 256, SMEM_MMA>>>(
        P_AY, P_WOUT, BUF_EXT, nullptr, P_AY2, nullptr, T_, DM_, DI_, DI_, 0);

    // 12. head (HMMA): out = y2 @ head_w^T + head_b
    gemm_mma<false><<<dim3(T_/128, V_/128), 256, SMEM_MMA>>>(
        P_AY2, P_WHEAD, BUF_EXT, out, P_NONE, head_b, T_, V_, DM_, DM_, 1);
}

// round 17
// speedup vs baseline: 1.7148x; 1.0069x over previous
#include <cuda_runtime.h>
#include <cuda_bf16.h>
#include <cstdint>
#include <math.h>

// Problem constants
#define B_   2
#define L_   2048
#define T_   4096        // B_*L_
#define DM_  1024
#define DI_  2048
#define DS_  16
#define DC_  4
#define DTR_ 64
#define V_   32000
#define DBC_ 96          // DTR + 2*DS

// ---------------- fp32 scratch ----------------
__device__ float g_xz [T_ * 2 * DI_];    // x | z
__device__ float g_x  [T_ * DI_];
__device__ float g_dbc[T_ * DBC_];
__device__ float g_dt [T_ * DI_];
__device__ float g_y  [T_ * DI_];

// ---------------- bf16 split scratch (hi/lo) ----------------
__device__ __nv_bfloat16 g_aemb_h[T_ * DM_],  g_aemb_l[T_ * DM_];
__device__ __nv_bfloat16 g_ax_h  [T_ * DI_],  g_ax_l  [T_ * DI_];
__device__ __nv_bfloat16 g_adt_h [T_ * DTR_], g_adt_l [T_ * DTR_];
__device__ __nv_bfloat16 g_ay_h  [T_ * DI_],  g_ay_l  [T_ * DI_];
__device__ __nv_bfloat16 g_ay2_h [T_ * DM_],  g_ay2_l [T_ * DM_];
__device__ __nv_bfloat16 g_win_h [2*DI_*DM_], g_win_l [2*DI_*DM_];
__device__ __nv_bfloat16 g_wxp_h [DBC_*DI_],  g_wxp_l [DBC_*DI_];
__device__ __nv_bfloat16 g_wdt_h [DI_*DTR_],  g_wdt_l [DI_*DTR_];
__device__ __nv_bfloat16 g_wout_h[DM_*DI_],   g_wout_l[DM_*DI_];
__device__ __nv_bfloat16 g_whead_h[(size_t)V_*DM_], g_whead_l[(size_t)V_*DM_];

// ---------------- selectors ----------------
enum Buf   { BUF_XZ = 0, BUF_X, BUF_DBC, BUF_DT, BUF_Y, BUF_EXT };
enum BPair { P_AEMB = 0, P_AX, P_ADT, P_AY, P_AY2,
             P_WIN, P_WXP, P_WDT, P_WOUT, P_WHEAD, P_NONE };

__device__ __forceinline__ float* buf_ptr_mut(int sel, float* ext) {
    switch (sel) {
        case BUF_XZ: return g_xz;   case BUF_X:  return g_x;
        case BUF_DBC: return g_dbc; case BUF_DT: return g_dt;
        case BUF_Y:  return g_y;    default:     return ext;
    }
}
__device__ __forceinline__ void bpair(int sel, __nv_bfloat16*& h, __nv_bfloat16*& l) {
    switch (sel) {
        case P_AEMB: h = g_aemb_h;  l = g_aemb_l;  break;
        case P_AX:   h = g_ax_h;    l = g_ax_l;    break;
        case P_ADT:  h = g_adt_h;   l = g_adt_l;   break;
        case P_AY:   h = g_ay_h;    l = g_ay_l;    break;
        case P_AY2:  h = g_ay2_h;   l = g_ay2_l;   break;
        case P_WIN:  h = g_win_h;   l = g_win_l;   break;
        case P_WXP:  h = g_wxp_h;   l = g_wxp_l;   break;
        case P_WDT:  h = g_wdt_h;   l = g_wdt_l;   break;
        case P_WOUT: h = g_wout_h;  l = g_wout_l;  break;
        case P_WHEAD: h = g_whead_h; l = g_whead_l; break;
        default:     h = nullptr;   l = nullptr;   break;
    }
}

// ---------------- math helpers ----------------
__device__ __forceinline__ float softplusf(float x) {
    return fmaxf(x, 0.f) + log1pf(__expf(-fabsf(x)));
}
__device__ __forceinline__ float siluf(float x) {
    return x / (1.f + __expf(-x));
}
__device__ __forceinline__ void split1(float x, __nv_bfloat16& h, __nv_bfloat16& l) {
    h = __float2bfloat16(x);
    l = __float2bfloat16(x - __bfloat162float(h));
}
__device__ __forceinline__ uint32_t smem_u32(const void* p) {
    uint32_t a;
    asm("{ .reg .u64 t; cvta.to.shared.u64 t, %1; cvt.u32.u64 %0, t; }" : "=r"(a) : "l"(p));
    return a;
}
__device__ __forceinline__ void cp16(uint32_t saddr, const void* g) {
    asm volatile("cp.async.cg.shared.global [%0], [%1], 16;" :: "r"(saddr), "l"(g));
}
__device__ __forceinline__ void cp16z(uint32_t saddr, const void* g, uint32_t srcsz) {
    asm volatile("cp.async.cg.shared.global [%0], [%1], 16, %2;"
                 :: "r"(saddr), "l"(g), "r"(srcsz));
}
__device__ __forceinline__ void ldsm4(uint32_t* r, uint32_t addr) {
    asm volatile("ldmatrix.sync.aligned.m8n8.x4.shared.b16 {%0,%1,%2,%3}, [%4];"
        : "=r"(r[0]), "=r"(r[1]), "=r"(r[2]), "=r"(r[3]) : "r"(addr));
}
__device__ __forceinline__ void mma16816(float* c, const uint32_t* a, uint32_t b0, uint32_t b1) {
    asm volatile("mma.sync.aligned.m16n8k16.row.col.f32.bf16.bf16.f32 "
        "{%0,%1,%2,%3}, {%4,%5,%6,%7}, {%8,%9}, {%0,%1,%2,%3};"
        : "+f"(c[0]), "+f"(c[1]), "+f"(c[2]), "+f"(c[3])
        : "r"(a[0]), "r"(a[1]), "r"(a[2]), "r"(a[3]), "r"(b0), "r"(b1));
}

// ---------------- elementwise kernels ----------------
#define N4_WIN  (2*DI_*DM_/4)
#define N4_WXP  (DBC_*DI_/4)
#define N4_WDT  (DI_*DTR_/4)
#define N4_WOUT (DM_*DI_/4)
#define N4_WHEAD (V_*DM_/4)
#define C1_ (N4_WIN)
#define C2_ (C1_ + N4_WXP)
#define C3_ (C2_ + N4_WDT)
#define C4_ (C3_ + N4_WOUT)
#define C5_ (C4_ + N4_WHEAD)

__global__ void wsplit_all_kernel(const float* __restrict__ win,
                                  const float* __restrict__ wxp,
                                  const float* __restrict__ wdt,
                                  const float* __restrict__ wout,
                                  const float* __restrict__ whead) {
    int i = blockIdx.x * blockDim.x + threadIdx.x;
    if (i >= C5_) return;
    const float* src; int sel; int j;
    if (i < C1_)      { src = win;   sel = P_WIN;   j = i; }
    else if (i < C2_) { src = wxp;   sel = P_WXP;   j = i - C1_; }
    else if (i < C3_) { src = wdt;   sel = P_WDT;   j = i - C2_; }
    else if (i < C4_) { src = wout;  sel = P_WOUT;  j = i - C3_; }
    else              { src = whead; sel = P_WHEAD; j = i - C4_; }
    __nv_bfloat16 *dh, *dl; bpair(sel, dh, dl);
    float4 v = reinterpret_cast<const float4*>(src)[j];
    __nv_bfloat16 h0, l0, h1, l1, h2, l2, h3, l3;
    split1(v.x, h0, l0); split1(v.y, h1, l1);
    split1(v.z, h2, l2); split1(v.w, h3, l3);
    reinterpret_cast<__nv_bfloat162*>(dh)[2*j]   = __nv_bfloat162(h0, h1);
    reinterpret_cast<__nv_bfloat162*>(dh)[2*j+1] = __nv_bfloat162(h2, h3);
    reinterpret_cast<__nv_bfloat162*>(dl)[2*j]   = __nv_bfloat162(l0, l1);
    reinterpret_cast<__nv_bfloat162*>(dl)[2*j+1] = __nv_bfloat162(l2, l3);
}

__global__ void gather_split_kernel(const int* __restrict__ tokens,
                                    const float* __restrict__ embed) {
    int i = blockIdx.x * blockDim.x + threadIdx.x;   // over T_*DM_/4
    int t = i >> 8, j = i & 255;
    int tok = tokens[t];
    float4 v = reinterpret_cast<const float4*>(embed)[tok * 256 + j];
    __nv_bfloat16 h0, l0, h1, l1, h2, l2, h3, l3;
    split1(v.x, h0, l0); split1(v.y, h1, l1);
    split1(v.z, h2, l2); split1(v.w, h3, l3);
    reinterpret_cast<__nv_bfloat162*>(g_aemb_h)[2*i]   = __nv_bfloat162(h0, h1);
    reinterpret_cast<__nv_bfloat162*>(g_aemb_h)[2*i+1] = __nv_bfloat162(h2, h3);
    reinterpret_cast<__nv_bfloat162*>(g_aemb_l)[2*i]   = __nv_bfloat162(l0, l1);
    reinterpret_cast<__nv_bfloat162*>(g_aemb_l)[2*i+1] = __nv_bfloat162(l2, l3);
}

__global__ void zero_dbc_kernel() {
    int i = blockIdx.x * blockDim.x + threadIdx.x;   // T_*DBC_/4
    reinterpret_cast<float4*>(g_dbc)[i] = make_float4(0.f, 0.f, 0.f, 0.f);
}

__global__ void split_dt_kernel() {
    int i = blockIdx.x * blockDim.x + threadIdx.x;   // over T_*16
    if (i >= T_ * 16) return;
    int t = i >> 4, c = (i & 15) * 4;
    float4 v = *reinterpret_cast<const float4*>(&g_dbc[(size_t)t * DBC_ + c]);
    __nv_bfloat16 h0, l0, h1, l1, h2, l2, h3, l3;
    split1(v.x, h0, l0); split1(v.y, h1, l1);
    split1(v.z, h2, l2); split1(v.w, h3, l3);
    size_t o = ((size_t)t * DTR_ + c) >> 1;
    reinterpret_cast<__nv_bfloat162*>(g_adt_h)[o]   = __nv_bfloat162(h0, h1);
    reinterpret_cast<__nv_bfloat162*>(g_adt_h)[o+1] = __nv_bfloat162(h2, h3);
    reinterpret_cast<__nv_bfloat162*>(g_adt_l)[o]   = __nv_bfloat162(l0, l1);
    reinterpret_cast<__nv_bfloat162*>(g_adt_l)[o+1] = __nv_bfloat162(l2, l3);
}

__global__ void conv_silu_kernel(const float* __restrict__ cw,
                                 const float* __restrict__ cb) {
    int i = blockIdx.x * blockDim.x + threadIdx.x;   // over T_*DI_
    int c = i & (DI_ - 1);
    int t = i >> 11;
    int l = t & (L_ - 1);
    float acc = cb[c];
#pragma unroll
    for (int k = 0; k < DC_; k++) {
        int ll = l - (DC_ - 1) + k;
        if (ll >= 0)
            acc = fmaf(cw[c * DC_ + k], g_xz[(size_t)(t - (DC_ - 1) + k) * (2 * DI_) + c], acc);
    }
    float v = siluf(acc);
    g_x[i] = v;
    __nv_bfloat16 h, lo; split1(v, h, lo);
    g_ax_h[i] = h; g_ax_l[i] = lo;
}

// selective scan with register prefetch pipeline (depth 4)
__global__ void scan_kernel(const float* __restrict__ A_log) {
    int s  = threadIdx.x & 15;
    int dl = threadIdx.x >> 4;
    int d  = blockIdx.x * 32 + dl;
    int b  = blockIdx.y;
    float a = -__expf(A_log[d * DS_ + s]);
    float h = 0.f;
    int t0 = b * L_;
    const float* dtp = g_dt  + (size_t)t0 * DI_ + d;
    const float* up  = g_x   + (size_t)t0 * DI_ + d;
    const float* bp  = g_dbc + (size_t)t0 * DBC_ + DTR_ + s;
    const float* cp  = bp + DS_;
    float*       yp  = g_y   + (size_t)t0 * DI_ + d;

    float pdt[4], pu[4], pB[4], pC[4];
#pragma unroll
    for (int j = 0; j < 4; j++) {
        pdt[j] = dtp[(size_t)j * DI_];
        pu[j]  = up [(size_t)j * DI_];
        pB[j]  = bp [(size_t)j * DBC_];
        pC[j]  = cp [(size_t)j * DBC_];
    }

    for (int l = 0; l < L_; l += 4) {
#pragma unroll
        for (int j = 0; j < 4; j++) {
            float dtv = pdt[j], uv = pu[j], Bv = pB[j], Cv = pC[j];
            int lp = l + 4 + j;
            int off = (lp < L_) ? lp : (L_ - 1);
            pdt[j] = dtp[(size_t)off * DI_];
            pu[j]  = up [(size_t)off * DI_];
            pB[j]  = bp [(size_t)off * DBC_];
            pC[j]  = cp [(size_t)off * DBC_];

            float dA = __expf(dtv * a);
            h = fmaf(dA, h, dtv * Bv * uv);
            float p = h * Cv;
            p += __shfl_xor_sync(0xffffffffu, p, 1);
            p += __shfl_xor_sync(0xffffffffu, p, 2);
            p += __shfl_xor_sync(0xffffffffu, p, 4);
            p += __shfl_xor_sync(0xffffffffu, p, 8);
            if (s == 0) yp[(size_t)(l + j) * DI_] = p;
        }
    }
}

__global__ void gate_split_kernel(const float* __restrict__ Dv) {
    int i = blockIdx.x * blockDim.x + threadIdx.x;   // over T_*DI_/2
    int e0 = 2 * i;
    int d = e0 & (DI_ - 1);
    int t = e0 >> 11;
    float2 y = *reinterpret_cast<const float2*>(&g_y[e0]);
    float2 x = *reinterpret_cast<const float2*>(&g_x[e0]);
    float2 z = *reinterpret_cast<const float2*>(&g_xz[(size_t)t * (2 * DI_) + DI_ + d]);
    float v0 = (y.x + x.x * Dv[d])     * siluf(z.x);
    float v1 = (y.y + x.y * Dv[d + 1]) * siluf(z.y);
    __nv_bfloat16 h0, l0, h1, l1;
    split1(v0, h0, l0); split1(v1, h1, l1);
    reinterpret_cast<__nv_bfloat162*>(g_ay_h)[i] = __nv_bfloat162(h0, h1);
    reinterpret_cast<__nv_bfloat162*>(g_ay_l)[i] = __nv_bfloat162(l0, l1);
}

// ---------------- HMMA split-bf16 GEMM (mma.sync m16n8k16) ----------------
// Mainloop: load(st+2) issued BEFORE compute (R13: lead time is load-bearing).
// ONE barrier per kt: the leading barrier of iteration kt+1 already orders
// every warp's compute(kt) before any load targeting stage kt%3 (3 stages).
// MMA products issued in rounds (hh, hl, lh) across (mt, cHalf) so same-
// accumulator touches are spaced by 3 independent MMAs.
// Tile 128x128xBK32, 8 warps (4m x 2n), warp tile 32x64, XOR-swizzled smem,
// 3 stages x 32KB = 96KB -> 2 CTAs/SM.
#define ARR_B   8192                       // 128 rows * 64B per array
#define STAGE_B (4 * ARR_B)                // 32768 bytes
#define SMEM_MMA (3 * STAGE_B)             // 98304 bytes

template<bool GX>
__global__ __launch_bounds__(256, 2)
void gemm_mma(int a_sel, int b_sel, int c_sel, float* __restrict__ C_ext,
              int pair_sel, const float* __restrict__ bias,
              int M, int N, int K, int KC, int epi) {
    extern __shared__ __nv_bfloat16 sm[];
    __nv_bfloat16 *Ah, *Al, *Bh, *Bl;
    bpair(a_sel, Ah, Al);
    bpair(b_sel, Bh, Bl);
    float* __restrict__ C = buf_ptr_mut(c_sel, C_ext);
    __nv_bfloat16 *Oh = nullptr, *Ol = nullptr;
    if (pair_sel != P_NONE) bpair(pair_sel, Oh, Ol);

    const int tid  = threadIdx.x;
    const int wid  = tid >> 5, lane = tid & 31;
    const int bm   = blockIdx.x * 128;
    const int bn   = blockIdx.y * 128;
    const int kbase = blockIdx.z * KC;
    const int wm   = wid & 3;                   // 4 m-warps of 32 rows
    const int wn   = wid >> 2;                  // 2 n-warps of 64 cols
    const int KT   = KC >> 5;

    const uint32_t sb0 = smem_u32(sm);

    auto load_stage = [&](int st, int kt) {
        const int k0 = kbase + kt * 32;
        const uint32_t sb = sb0 + st * STAGE_B;
#pragma unroll
        for (int ii = 0; ii < 8; ii++) {
            int i   = tid + ii * 256;
            int arr = i >> 9;
            int r   = (i >> 2) & 127;
            int cc  = i & 3;
            const __nv_bfloat16* src = (arr == 0) ? Ah : (arr == 1) ? Al
                                     : (arr == 2) ? Bh : Bl;
            uint32_t dst = sb + (uint32_t)(arr * ARR_B + r * 64
                                           + ((cc ^ ((r >> 1) & 3)) << 4));
            if (GX && arr >= 2) {
                int grow = bn + r;
                uint32_t ok = (grow < N) ? 16u : 0u;
                int ge = (grow < N) ? grow : 0;
                cp16z(dst, src + (size_t)ge * K + k0 + cc * 8, ok);
            } else {
                int grow = (arr < 2 ? bm : bn) + r;
                cp16(dst, src + (size_t)grow * K + k0 + cc * 8);
            }
        }
    };

    float acc[2][8][4];
#pragma unroll
    for (int i = 0; i < 2; i++)
#pragma unroll
        for (int j = 0; j < 8; j++)
#pragma unroll
            for (int k = 0; k < 4; k++) acc[i][j][k] = 0.f;

    // prologue: stages 0,1
    load_stage(0, 0);
    asm volatile("cp.async.commit_group;" ::: "memory");
    if (KT > 1) load_stage(1, 1);
    asm volatile("cp.async.commit_group;" ::: "memory");

    const int a_r = (lane & 15);
    const int ca  = (lane >> 4);
    const int b_r = ((lane >> 3) & 1) * 8 + (lane & 7);
    const int cb  = (lane >> 4);

    int st = 0;
    for (int kt = 0; kt < KT; kt++) {
        asm volatile("cp.async.wait_group 1;" ::: "memory");
        __syncthreads();
        // refill two stages ahead BEFORE compute (overlaps this iter's MMAs)
        if (kt + 2 < KT) {
            int st2 = st + 2; if (st2 >= 3) st2 -= 3;
            load_stage(st2, kt + 2);
        }
        asm volatile("cp.async.commit_group;" ::: "memory");

        const uint32_t sb = sb0 + st * STAGE_B;
#pragma unroll
        for (int k16 = 0; k16 < 2; k16++) {
            uint32_t ah[2][4], al[2][4];
#pragma unroll
            for (int mt = 0; mt < 2; mt++) {
                int row = wm * 32 + mt * 16 + a_r;
                int cc  = 2 * k16 + ca;
                uint32_t off = (uint32_t)(row * 64 + ((cc ^ ((row >> 1) & 3)) << 4));
                ldsm4(ah[mt], sb + off);
                ldsm4(al[mt], sb + ARR_B + off);
            }
#pragma unroll
            for (int nt2 = 0; nt2 < 4; nt2++) {
                int row = wn * 64 + nt2 * 16 + b_r;
                int cc  = 2 * k16 + cb;
                uint32_t off = (uint32_t)(row * 64 + ((cc ^ ((row >> 1) & 3)) << 4));
                uint32_t bh[4], bl[4];
                ldsm4(bh, sb + 2 * ARR_B + off);
                ldsm4(bl, sb + 3 * ARR_B + off);
                float* c00 = acc[0][nt2 * 2];
                float* c01 = acc[0][nt2 * 2 + 1];
                float* c10 = acc[1][nt2 * 2];
                float* c11 = acc[1][nt2 * 2 + 1];
                // round 1: Ah x Bh (4 independent MMAs)
                mma16816(c00, ah[0], bh[0], bh[2]);
                mma16816(c01, ah[0], bh[1], bh[3]);
                mma16816(c10, ah[1], bh[0], bh[2]);
                mma16816(c11, ah[1], bh[1], bh[3]);
                // round 2: Ah x Bl
                mma16816(c00, ah[0], bl[0], bl[2]);
                mma16816(c01, ah[0], bl[1], bl[3]);
                mma16816(c10, ah[1], bl[0], bl[2]);
                mma16816(c11, ah[1], bl[1], bl[3]);
                // round 3: Al x Bh
                mma16816(c00, al[0], bh[0], bh[2]);
                mma16816(c01, al[0], bh[1], bh[3]);
                mma16816(c10, al[1], bh[0], bh[2]);
                mma16816(c11, al[1], bh[1], bh[3]);
            }
        }
        // no trailing barrier: next iteration's leading barrier provides the
        // producer-consumer ordering (3-stage ring keeps write targets disjoint)
        if (++st == 3) st = 0;
    }

    // epilogue
    const int er = bm + wm * 32 + (lane >> 2);
    const int ec = bn + wn * 64 + (lane & 3) * 2;
#pragma unroll
    for (int mt = 0; mt < 2; mt++) {
#pragma unroll
        for (int nt = 0; nt < 8; nt++) {
            int col = ec + nt * 8;
            if (GX) {
                if (col >= N) continue;
#pragma unroll
                for (int half = 0; half < 2; half++) {
                    int row = er + mt * 16 + half * 8;
                    atomicAdd(&C[(size_t)row * N + col],     acc[mt][nt][half * 2 + 0]);
                    atomicAdd(&C[(size_t)row * N + col + 1], acc[mt][nt][half * 2 + 1]);
                }
            } else {
                float b0 = 0.f, b1 = 0.f;
                if (epi >= 1) { b0 = bias[col]; b1 = bias[col + 1]; }
#pragma unroll
                for (int half = 0; half < 2; half++) {
                    int row = er + mt * 16 + half * 8;
                    float v0 = acc[mt][nt][half * 2 + 0] + b0;
                    float v1 = acc[mt][nt][half * 2 + 1] + b1;
                    if (epi == 2) { v0 = softplusf(v0); v1 = softplusf(v1); }
                    if (pair_sel != P_NONE) {
                        __nv_bfloat16 h0, l0, h1, l1;
                        split1(v0, h0, l0); split1(v1, h1, l1);
                        size_t o = ((size_t)row * N + col) >> 1;
                        reinterpret_cast<__nv_bfloat162*>(Oh)[o] = __nv_bfloat162(h0, h1);
                        reinterpret_cast<__nv_bfloat162*>(Ol)[o] = __nv_bfloat162(l0, l1);
                    } else {
                        *reinterpret_cast<float2*>(&C[(size_t)row * N + col]) =
                            make_float2(v0, v1);
                    }
                }
            }
        }
    }
}

// ---------------- launch ----------------
extern "C" void kernel_launch(void* const* d_in, const int* in_sizes, int n_in,
                              void* d_out, int out_size) {
    const int*   tokens     = (const int*)  d_in[0];
    const float* embed      = (const float*)d_in[1];
    const float* in_proj_w  = (const float*)d_in[2];
    const float* conv_w     = (const float*)d_in[3];
    const float* conv_b     = (const float*)d_in[4];
    const float* x_proj_w   = (const float*)d_in[5];
    const float* dt_proj_w  = (const float*)d_in[6];
    const float* dt_proj_b  = (const float*)d_in[7];
    const float* A_log      = (const float*)d_in[8];
    const float* Dv         = (const float*)d_in[9];
    const float* out_proj_w = (const float*)d_in[10];
    const float* head_w     = (const float*)d_in[11];
    const float* head_b     = (const float*)d_in[12];
    float* out = (float*)d_out;

    cudaFuncSetAttribute(gemm_mma<false>, cudaFuncAttributeMaxDynamicSharedMemorySize, SMEM_MMA);
    cudaFuncSetAttribute(gemm_mma<true>,  cudaFuncAttributeMaxDynamicSharedMemorySize, SMEM_MMA);

    // 1. all weight splits (one launch)
    wsplit_all_kernel<<<(C5_ + 255) / 256, 256>>>(in_proj_w, x_proj_w, dt_proj_w,
                                                  out_proj_w, head_w);

    // 2. embedding gather + split (fused)
    gather_split_kernel<<<(T_ * DM_ / 4) / 256, 256>>>(tokens, embed);

    // 3. zero dbc accumulator (for x_proj split-K atomics)
    zero_dbc_kernel<<<(T_ * DBC_ / 4) / 256, 256>>>();

    // 4. in_proj (HMMA, fast path) -- profiler capture slot
    gemm_mma<false><<<dim3(T_/128, 2*DI_/128), 256, SMEM_MMA>>>(
        P_AEMB, P_WIN, BUF_XZ, nullptr, P_NONE, nullptr, T_, 2*DI_, DM_, DM_, 0);

    // 5. causal conv + SiLU + split (fused)
    conv_silu_kernel<<<(T_ * DI_) / 256, 256>>>(conv_w, conv_b);

    // 6. x_proj (HMMA guarded, split-K=8): dbc += x @ x_proj_w^T
    gemm_mma<true><<<dim3(T_/128, 1, 8), 256, SMEM_MMA>>>(
        P_AX, P_WXP, BUF_DBC, nullptr, P_NONE, nullptr, T_, DBC_, DI_, DI_/8, 0);

    // 7. dt input split
    split_dt_kernel<<<(T_*16 + 255)/256, 256>>>();

    // 8. dt (HMMA): dt = softplus(dbc[:, :64] @ dt_proj_w^T + b)
    gemm_mma<false><<<dim3(T_/128, DI_/128), 256, SMEM_MMA>>>(
        P_ADT, P_WDT, BUF_DT, nullptr, P_NONE, dt_proj_b, T_, DI_, DTR_, DTR_, 2);

    // 9. selective scan (prefetch depth 4)
    scan_kernel<<<dim3(DI_/32, B_), 512>>>(A_log);

    // 10. gating + split (fused)
    gate_split_kernel<<<(T_ * DI_ / 2) / 256, 256>>>(Dv);

    // 11. out_proj (HMMA, split-pair epilogue): ay2 = split(y @ out_proj_w^T)
    gemm_mma<false><<<dim3(T_/128, DM_/128), 256, SMEM_MMA>>>(
        P_AY, P_WOUT, BUF_EXT, nullptr, P_AY2, nullptr, T_, DM_, DI_, DI_, 0);

    // 12. head (HMMA): out = y2 @ head_w^T + head_b
    gemm_mma<false><<<dim3(T_/128, V_/128), 256, SMEM_MMA>>>(
        P_AY2, P_WHEAD, BUF_EXT, out, P_NONE, head_b, T_, V_, DM_, DM_, 1);
}